// round 17
// baseline (speedup 1.0000x reference)
#include <cuda_runtime.h>

// Janossy pooling, k=2, n=2048, d=32 — ONE kernel, tiled pair-sum.
// R15 structure with halved key slice: grid 256 = 16 itiles x 16 jtiles,
// JT=128 keys/block, block 256 = 8 warps x 16 rows. Per-block L1tex chain
// drops from ~384 to ~256 wavefronts. Atomic-free block reduction +
// v4 REDG epilogue + STG.128 zeroing kept verbatim.
//
// out[1][d] = (1/C) sum_i r_i x_i[d],  out[0][d] = (1/C) sum_i (n-1-r_i) x_i[d]
// Keys pairwise distinct (iid float32 normals) -> strict '<' counting gives
// the exact stable rank (validated since R9). Partial count c per row against
// this block's 128-key slice; complement algebraic:
// acc0 = (128 - [rows in slice])*Σx - acc1, rows-in-slice iff itile == jtile.
//
// Replay-safe zeroing: graph replays are stream-serialized, so block 0/warp 1
// zeroes out[0:64] with STG.128 after its loads issue, threadfence (release),
// bumps monotone g_zflag. Warp 0 of each block takes a monotone ticket
// (epoch = tick/GRID) and acquire-polls g_zflag >= epoch+1 BEFORE compute;
// program order puts the final v4 RED.ADDs (also warp 0) after the acquire.

#define NROWS 2048
#define NDIM  32
#define BLOCK 256                 // 8 warps x 16 rows = 128 rows per block
#define NWARP 8
#define JT    128                 // keys per j-slice
#define GRID  256                 // 16 itiles x 16 jtiles

__device__ unsigned int g_start;  // monotone entry ticket
__device__ unsigned int g_zflag;  // monotone "out zeroed" epoch counter

__global__ __launch_bounds__(BLOCK) void janossy_jt128(const float* __restrict__ X,
                                                       float* __restrict__ out) {
    __shared__ float skeys[JT];
    __shared__ float spart[NWARP][2 * NDIM];   // per-warp partials (no atomics)
    __shared__ float sfin[2 * NDIM];           // repack for v4 REDG

    const int tid   = threadIdx.x;
    const int warp  = tid >> 5;
    const int lane  = tid & 31;
    const int itile = blockIdx.x >> 4;     // 0..15 (128 rows each)
    const int jtile = blockIdx.x & 15;     // 0..15 (128 keys each)

    // ---- 1) Issue ALL global loads first (fly while protocol runs).
    float kj = 0.0f;
    if (tid < JT) kj = X[(jtile * JT + tid) * NDIM];         // strided key slice

    const int rbase = itile * 128 + warp * 16;
    float xr[16];
    #pragma unroll
    for (int t = 0; t < 16; t++) xr[t] = X[(rbase + t) * NDIM + lane];

    // ---- 2) Protocol work overlapped with loads in flight.
    if (blockIdx.x == 0 && warp == 1) {    // zero out[0:64] with 16 STG.128
        if (lane < 16) {
            const float4 z = make_float4(0.0f, 0.0f, 0.0f, 0.0f);
            *reinterpret_cast<float4*>(&out[lane * 4]) = z;
        }
        __syncwarp();
        __threadfence();                   // release zeros before flag
        if (lane == 0) atomicAdd(&g_zflag, 1u);
    }
    if (warp == 0) {                       // ticket -> epoch, acquire-poll flag
        unsigned target;
        if (lane == 0) target = atomicAdd(&g_start, 1u) / GRID + 1u;
        target = __shfl_sync(0xffffffffu, target, 0);
        unsigned v;
        do {
            asm volatile("ld.acquire.gpu.u32 %0, [%1];" : "=r"(v) : "l"(&g_zflag));
        } while (v < target);
    }

    // ---- 3) Stage keys, sync.
    if (tid < JT) skeys[tid] = kj;
    __syncthreads();

    // ---- 4) Compute: strict-< partial rank counts (1 float4 LDS per row).
    const float4* sk4 = reinterpret_cast<const float4*>(skeys);
    float acc1 = 0.0f, sx = 0.0f;          // lane == feature dim

    #pragma unroll
    for (int t = 0; t < 16; t++) {
        const float x  = xr[t];
        const float xi = __shfl_sync(0xffffffffu, x, 0);   // key_i = x_i[0]

        const float4 kv = sk4[lane];                       // LDS.128, conflict-free
        int cnt = (int)(kv.x < xi);
        cnt    += (int)(kv.y < xi);
        cnt    += (int)(kv.z < xi);
        cnt    += (int)(kv.w < xi);

        const int c = __reduce_add_sync(0xffffffffu, cnt); // partial rank
        acc1 += (float)c * x;
        sx   += x;
    }

    // Complement: this block's rows lie in its key slice iff itile == jtile.
    const float diag = (float)(JT - (int)(itile == jtile));
    const float invC = 1.0f / 2096128.0f;

    // ---- 5) Atomic-free block reduction: plain STS of per-warp partials.
    spart[warp][lane]        = (diag * sx - acc1) * invC;  // acc0 slot
    spart[warp][lane + NDIM] = acc1 * invC;                // acc1 slot
    __syncthreads();

    // ---- 6) Warp 0: tree-sum the 8 partials, repack, v4 RED.ADD.
    if (warp == 0) {
        float f0 = 0.0f, f1 = 0.0f;
        #pragma unroll
        for (int w = 0; w < NWARP; w++) {
            f0 += spart[w][lane];
            f1 += spart[w][lane + NDIM];
        }
        sfin[lane]        = f0;
        sfin[lane + NDIM] = f1;
        __syncwarp();
        if (lane < 16) {
            const float4 v = *reinterpret_cast<const float4*>(&sfin[lane * 4]);
            asm volatile("red.global.add.v4.f32 [%0], {%1, %2, %3, %4};"
                         :: "l"(&out[lane * 4]),
                            "f"(v.x), "f"(v.y), "f"(v.z), "f"(v.w)
                         : "memory");
        }
    }
}

extern "C" void kernel_launch(void* const* d_in, const int* in_sizes, int n_in,
                              void* d_out, int out_size) {
    const float* X = (const float*)d_in[0];
    janossy_jt128<<<GRID, BLOCK>>>(X, (float*)d_out);
}